// round 1
// baseline (speedup 1.0000x reference)
#include <cuda_runtime.h>
#include <math.h>

// ---------------- problem constants ----------------
#define BB     32
#define HH     56
#define WWI    56
#define DIMC   512
#define WSZ    7
#define SHF    3
#define NHEAD  16
#define HDIM   32
#define MLPD   2048
#define SQ     49          // WSZ*WSZ
#define NWIN   64          // (56/7)^2
#define TOK    (BB*HH*WWI) // 100352
#define WTOT   (BB*NWIN)   // 2048

// ---------------- scratch (static device globals; allocation-free) -------
__device__ float g_win [TOK * DIMC];        // LN1 + window-partitioned
__device__ float g_qkv [TOK * 3 * DIMC];    // qkv projections
__device__ float g_att [TOK * DIMC];        // attention output (window order)
__device__ float g_proj[TOK * DIMC];        // proj GEMM output (window order)
__device__ float g_x1  [TOK * DIMC];        // first residual (image order)
__device__ float g_ln2 [TOK * DIMC];        // LN2 output
__device__ float g_mlp1[TOK * MLPD];        // gelu(h2 @ w1 + b1)

__device__ __forceinline__ float gelu_f(float x) {
    return 0.5f * x * (1.0f + erff(x * 0.70710678118654752f));
}

// ---------------- LayerNorm (+ optional roll+window gather) --------------
// One warp per output token. gather=1: output in window order, source is
// rolled image position. gather=0: identity mapping (LN2).
__global__ void ln_kernel(const float* __restrict__ src,
                          const float* __restrict__ gamma,
                          const float* __restrict__ beta,
                          float* __restrict__ dst, int gather)
{
    int gw = (blockIdx.x * blockDim.x + threadIdx.x) >> 5;
    if (gw >= TOK) return;
    int lane = threadIdx.x & 31;

    int srow;
    if (gather) {
        int w  = gw / SQ, s = gw - w * SQ;
        int bb = w >> 6, nw = w & 63;
        int wy = nw >> 3, wx = nw & 7;
        int iy = s / WSZ, ix = s - iy * WSZ;
        int row = wy * WSZ + iy + SHF; if (row >= HH)  row -= HH;
        int col = wx * WSZ + ix + SHF; if (col >= WWI) col -= WWI;
        srow = (bb * HH + row) * WWI + col;
    } else {
        srow = gw;
    }

    const float4* sp = (const float4*)(src + (size_t)srow * DIMC);
    float4 v[4];
    float sum = 0.f, sq = 0.f;
#pragma unroll
    for (int i = 0; i < 4; i++) {
        v[i] = sp[lane + i * 32];
        sum += v[i].x + v[i].y + v[i].z + v[i].w;
        sq  += v[i].x*v[i].x + v[i].y*v[i].y + v[i].z*v[i].z + v[i].w*v[i].w;
    }
#pragma unroll
    for (int o = 16; o > 0; o >>= 1) {
        sum += __shfl_xor_sync(0xffffffffu, sum, o);
        sq  += __shfl_xor_sync(0xffffffffu, sq,  o);
    }
    float mean = sum * (1.0f / DIMC);
    float var  = sq  * (1.0f / DIMC) - mean * mean;
    float inv  = rsqrtf(var + 1e-5f);

    float4* dp = (float4*)(dst + (size_t)gw * DIMC);
    const float4* gp = (const float4*)gamma;
    const float4* bp = (const float4*)beta;
#pragma unroll
    for (int i = 0; i < 4; i++) {
        float4 g = gp[lane + i * 32];
        float4 b = bp[lane + i * 32];
        float4 o;
        o.x = (v[i].x - mean) * inv * g.x + b.x;
        o.y = (v[i].y - mean) * inv * g.y + b.y;
        o.z = (v[i].z - mean) * inv * g.z + b.z;
        o.w = (v[i].w - mean) * inv * g.w + b.w;
        dp[lane + i * 32] = o;
    }
}

// ---------------- SGEMM 128x128x16, 256 threads, 8x8 micro-tile ----------
// EPI: 0 = +bias ; 1 = gelu(+bias) ; 2 = +bias + add (residual)
template<int EPI>
__global__ void __launch_bounds__(256, 2)
sgemm_kernel(const float* __restrict__ A, const float* __restrict__ Bm,
             const float* __restrict__ bias, const float* __restrict__ add,
             float* __restrict__ C, int M, int N, int K)
{
    const int BM = 128, BN = 128, BK = 16;
    __shared__ float As[BK][BM + 4];
    __shared__ float Bs[BK][BN];

    int bm0 = blockIdx.y * BM, bn0 = blockIdx.x * BN;
    int tid = threadIdx.x;
    int tx = tid & 15, ty = tid >> 4;

    float acc[8][8];
#pragma unroll
    for (int i = 0; i < 8; i++)
#pragma unroll
        for (int j = 0; j < 8; j++) acc[i][j] = 0.f;

    for (int k0 = 0; k0 < K; k0 += BK) {
#pragma unroll
        for (int l = 0; l < 2; l++) {
            int f = tid + l * 256;                 // 0..511
            // A tile: 128 rows x 16 cols = 512 float4
            int arow = f >> 2, akc = (f & 3) << 2;
            float4 a = *(const float4*)(A + (size_t)(bm0 + arow) * K + k0 + akc);
            As[akc + 0][arow] = a.x;
            As[akc + 1][arow] = a.y;
            As[akc + 2][arow] = a.z;
            As[akc + 3][arow] = a.w;
            // B tile: 16 rows x 128 cols = 512 float4
            int brow = f >> 5, bnc = (f & 31) << 2;
            *(float4*)&Bs[brow][bnc] =
                *(const float4*)(Bm + (size_t)(k0 + brow) * N + bn0 + bnc);
        }
        __syncthreads();

#pragma unroll
        for (int k = 0; k < BK; k++) {
            float a[8], b[8];
            *(float4*)(a)     = *(float4*)&As[k][ty * 8];
            *(float4*)(a + 4) = *(float4*)&As[k][ty * 8 + 4];
            *(float4*)(b)     = *(float4*)&Bs[k][tx * 8];
            *(float4*)(b + 4) = *(float4*)&Bs[k][tx * 8 + 4];
#pragma unroll
            for (int i = 0; i < 8; i++)
#pragma unroll
                for (int j = 0; j < 8; j++)
                    acc[i][j] += a[i] * b[j];
        }
        __syncthreads();
    }

#pragma unroll
    for (int i = 0; i < 8; i++) {
        int r = bm0 + ty * 8 + i;
#pragma unroll
        for (int j = 0; j < 8; j += 4) {
            int c = bn0 + tx * 8 + j;
            float4 o;
            o.x = acc[i][j]; o.y = acc[i][j+1]; o.z = acc[i][j+2]; o.w = acc[i][j+3];
            if (bias) {
                float4 bv = *(const float4*)(bias + c);
                o.x += bv.x; o.y += bv.y; o.z += bv.z; o.w += bv.w;
            }
            if (EPI == 1) {
                o.x = gelu_f(o.x); o.y = gelu_f(o.y);
                o.z = gelu_f(o.z); o.w = gelu_f(o.w);
            }
            if (EPI == 2) {
                float4 av = *(const float4*)(add + (size_t)r * N + c);
                o.x += av.x; o.y += av.y; o.z += av.z; o.w += av.w;
            }
            *(float4*)(C + (size_t)r * N + c) = o;
        }
    }
}

// ---------------- attention: one block per (window, head) ----------------
__global__ void __launch_bounds__(256)
attn_kernel(const float* __restrict__ qkv, const float* __restrict__ rel_bias,
            float* __restrict__ out)
{
    int w = blockIdx.x >> 4;        // window 0..2047
    int h = blockIdx.x & 15;        // head   0..15

    __shared__ float sq[SQ][HDIM + 1];
    __shared__ float sk[SQ][HDIM + 1];
    __shared__ float sv[SQ][HDIM + 1];
    __shared__ float sp[8][64];
    __shared__ int   sm[SQ];

    const float scale = 0.17677669529663689f;  // 1/sqrt(32)
    int tid = threadIdx.x;

    // load q,k,v tiles for this (window, head)
    for (int i = tid; i < SQ * HDIM; i += 256) {
        int s = i >> 5, d = i & 31;
        size_t base = ((size_t)(w * SQ + s)) * (3 * DIMC) + h * HDIM + d;
        sq[s][d] = qkv[base] * scale;
        sk[s][d] = qkv[base + DIMC];
        sv[s][d] = qkv[base + 2 * DIMC];
    }
    // mask region classes for this window
    if (tid < SQ) {
        int nw = w & 63;
        int wy = nw >> 3, wx = nw & 7;
        int r = wy * WSZ + tid / WSZ;
        int c = wx * WSZ + tid % WSZ;
        int mr = (r < 49) ? 0 : ((r < 53) ? 1 : 2);
        int mc = (c < 49) ? 0 : ((c < 53) ? 1 : 2);
        sm[tid] = mr * 3 + mc;
    }
    __syncthreads();

    int wp = tid >> 5, lane = tid & 31;

    for (int i = wp; i < SQ; i += 8) {
        int yi = i / WSZ, xi = i - yi * WSZ;
        int mi = sm[i];

        // two score columns per lane: j = lane, lane+32
        float s1 = 0.f, s2 = -1e30f;
        {
            int j = lane;
            float acc = 0.f;
#pragma unroll
            for (int d = 0; d < HDIM; d++) acc += sq[i][d] * sk[j][d];
            int yj = j / WSZ, xj = j - yj * WSZ;
            int rpi = (yi - yj + 6) * 13 + (xi - xj + 6);
            acc += rel_bias[rpi * NHEAD + h];
            if (sm[j] != mi) acc -= 100.0f;
            s1 = acc;
        }
        int j2 = lane + 32;
        if (j2 < SQ) {
            float acc = 0.f;
#pragma unroll
            for (int d = 0; d < HDIM; d++) acc += sq[i][d] * sk[j2][d];
            int yj = j2 / WSZ, xj = j2 - yj * WSZ;
            int rpi = (yi - yj + 6) * 13 + (xi - xj + 6);
            acc += rel_bias[rpi * NHEAD + h];
            if (sm[j2] != mi) acc -= 100.0f;
            s2 = acc;
        }

        float m = fmaxf(s1, s2);
#pragma unroll
        for (int o = 16; o > 0; o >>= 1) m = fmaxf(m, __shfl_xor_sync(0xffffffffu, m, o));
        float e1 = expf(s1 - m);
        float e2 = (j2 < SQ) ? expf(s2 - m) : 0.f;
        float sum = e1 + e2;
#pragma unroll
        for (int o = 16; o > 0; o >>= 1) sum += __shfl_xor_sync(0xffffffffu, sum, o);
        float rinv = 1.0f / sum;

        sp[wp][lane] = e1 * rinv;
        if (j2 < 64) sp[wp][j2] = (j2 < SQ) ? e2 * rinv : 0.f;
        __syncwarp();

        // out[i][d] for d = lane
        float acc = 0.f;
#pragma unroll
        for (int j = 0; j < SQ; j++) acc += sp[wp][j] * sv[j][lane];
        out[((size_t)(w * SQ + i)) * DIMC + h * HDIM + lane] = acc;
        __syncwarp();
    }
}

// ---------------- proj scatter: window-reverse + unroll + skip + bias ----
__global__ void scatter_kernel(const float* __restrict__ proj,
                               const float* __restrict__ pb,
                               const float* __restrict__ x,
                               float* __restrict__ x1)
{
    int t = blockIdx.x;                 // window-order token
    int tid = threadIdx.x;              // 128 threads, float4
    int w  = t / SQ, s = t - w * SQ;
    int bb = w >> 6, nw = w & 63;
    int wy = nw >> 3, wx = nw & 7;
    int iy = s / WSZ, ix = s - iy * WSZ;
    int row = wy * WSZ + iy + SHF; if (row >= HH)  row -= HH;
    int col = wx * WSZ + ix + SHF; if (col >= WWI) col -= WWI;
    size_t dst = ((size_t)((bb * HH + row) * WWI + col)) * DIMC;

    float4 pv = ((const float4*)(proj + (size_t)t * DIMC))[tid];
    float4 bv = ((const float4*)pb)[tid];
    float4 xv = ((const float4*)(x + dst))[tid];
    float4 o;
    o.x = xv.x + pv.x + bv.x;
    o.y = xv.y + pv.y + bv.y;
    o.z = xv.z + pv.z + bv.z;
    o.w = xv.w + pv.w + bv.w;
    ((float4*)(x1 + dst))[tid] = o;
}

// ---------------- launch --------------------------------------------------
extern "C" void kernel_launch(void* const* d_in, const int* in_sizes, int n_in,
                              void* d_out, int out_size)
{
    const float* x      = (const float*)d_in[0];
    const float* qkv_w  = (const float*)d_in[1];
    const float* qkv_b  = (const float*)d_in[2];
    const float* proj_w = (const float*)d_in[3];
    const float* proj_b = (const float*)d_in[4];
    const float* relb   = (const float*)d_in[5];
    const float* n1g    = (const float*)d_in[6];
    const float* n1b    = (const float*)d_in[7];
    const float* n2g    = (const float*)d_in[8];
    const float* n2b    = (const float*)d_in[9];
    const float* w1     = (const float*)d_in[10];
    const float* b1     = (const float*)d_in[11];
    const float* w2     = (const float*)d_in[12];
    const float* b2     = (const float*)d_in[13];
    float* out = (float*)d_out;

    float *win, *qkvs, *att, *proj, *x1, *ln2s, *mlp1;
    cudaGetSymbolAddress((void**)&win,  g_win);
    cudaGetSymbolAddress((void**)&qkvs, g_qkv);
    cudaGetSymbolAddress((void**)&att,  g_att);
    cudaGetSymbolAddress((void**)&proj, g_proj);
    cudaGetSymbolAddress((void**)&x1,   g_x1);
    cudaGetSymbolAddress((void**)&ln2s, g_ln2);
    cudaGetSymbolAddress((void**)&mlp1, g_mlp1);

    const int lnBlocks = (TOK * 32 + 255) / 256;   // one warp per token

    // 1. LN1 + roll + window partition
    ln_kernel<<<lnBlocks, 256>>>(x, n1g, n1b, win, 1);

    // 2. QKV GEMM  [TOK,512] x [512,1536]
    sgemm_kernel<0><<<dim3(1536 / 128, TOK / 128), 256>>>(
        win, qkv_w, qkv_b, nullptr, qkvs, TOK, 1536, DIMC);

    // 3. windowed attention
    attn_kernel<<<WTOT * NHEAD, 256>>>(qkvs, relb, att);

    // 4. proj GEMM  [TOK,512] x [512,512]  (bias applied in scatter)
    sgemm_kernel<0><<<dim3(DIMC / 128, TOK / 128), 256>>>(
        att, proj_w, nullptr, nullptr, proj, TOK, DIMC, DIMC);

    // 5. window reverse + unshift + skip + proj bias -> x1
    scatter_kernel<<<TOK, 128>>>(proj, proj_b, x, x1);

    // 6. LN2
    ln_kernel<<<lnBlocks, 256>>>(x1, n2g, n2b, ln2s, 0);

    // 7. MLP1 GEMM + exact GELU  [TOK,512] x [512,2048]
    sgemm_kernel<1><<<dim3(MLPD / 128, TOK / 128), 256>>>(
        ln2s, w1, b1, nullptr, mlp1, TOK, MLPD, DIMC);

    // 8. MLP2 GEMM + bias + residual -> out  [TOK,2048] x [2048,512]
    sgemm_kernel<2><<<dim3(DIMC / 128, TOK / 128), 256>>>(
        mlp1, w2, b2, x1, out, TOK, DIMC, MLPD);
}

// round 3
// speedup vs baseline: 2.0830x; 2.0830x over previous
#include <cuda_runtime.h>
#include <cuda_bf16.h>
#include <cstdint>
#include <math.h>

// ---------------- problem constants ----------------
#define BB     32
#define HH     56
#define WWI    56
#define DIMC   512
#define WSZ    7
#define SHF    3
#define NHEAD  16
#define HDIM   32
#define MLPD   2048
#define SQ     49
#define TOK    (BB*HH*WWI)   // 100352
#define WTOT   (BB*64)       // 2048

// weight-transpose offsets (elements) in the packed wT arrays
#define OW_QKV  0
#define OW_PROJ (512*1536)
#define OW_W1   (OW_PROJ + 512*512)
#define OW_W2   (OW_W1 + 512*2048)
#define WT_TOT  (OW_W2 + 2048*512)

// ---------------- scratch ----------------
__device__ __nv_bfloat16 g_wt_h [WT_TOT];
__device__ __nv_bfloat16 g_wt_l [WT_TOT];
__device__ __nv_bfloat16 g_win_h[(size_t)TOK*DIMC];
__device__ __nv_bfloat16 g_win_l[(size_t)TOK*DIMC];
__device__ float         g_qkv  [(size_t)TOK*3*DIMC];
__device__ __nv_bfloat16 g_att_h[(size_t)TOK*DIMC];
__device__ __nv_bfloat16 g_att_l[(size_t)TOK*DIMC];
__device__ float         g_x1   [(size_t)TOK*DIMC];
__device__ __nv_bfloat16 g_ln2_h[(size_t)TOK*DIMC];
__device__ __nv_bfloat16 g_ln2_l[(size_t)TOK*DIMC];
__device__ __nv_bfloat16 g_m1_h [(size_t)TOK*MLPD];
__device__ __nv_bfloat16 g_m1_l [(size_t)TOK*MLPD];

__device__ __forceinline__ float gelu_f(float x) {
    return 0.5f * x * (1.0f + erff(x * 0.70710678118654752f));
}

// ---------------- PTX helpers (sm_80-era: valid on base sm_103) ----------
__device__ __forceinline__ uint32_t smem_u32(const void* p) {
    uint32_t a;
    asm("{ .reg .u64 t; cvta.to.shared.u64 t, %1; cvt.u32.u64 %0, t; }" : "=r"(a) : "l"(p));
    return a;
}
__device__ __forceinline__ void cpa16(uint32_t s, const void* g) {
    asm volatile("cp.async.cg.shared.global [%0], [%1], 16;" :: "r"(s), "l"(g));
}
__device__ __forceinline__ void cp_commit() {
    asm volatile("cp.async.commit_group;" ::: "memory");
}
__device__ __forceinline__ void ldx4(uint32_t* r, uint32_t a) {
    asm volatile("ldmatrix.sync.aligned.m8n8.x4.shared.b16 {%0,%1,%2,%3}, [%4];"
        : "=r"(r[0]), "=r"(r[1]), "=r"(r[2]), "=r"(r[3]) : "r"(a));
}
__device__ __forceinline__ void ldx2(uint32_t* r, uint32_t a) {
    asm volatile("ldmatrix.sync.aligned.m8n8.x2.shared.b16 {%0,%1}, [%2];"
        : "=r"(r[0]), "=r"(r[1]) : "r"(a));
}
__device__ __forceinline__ void mma16816(float* d, const uint32_t* a, const uint32_t* b) {
    asm volatile("mma.sync.aligned.m16n8k16.row.col.f32.bf16.bf16.f32 "
        "{%0,%1,%2,%3}, {%4,%5,%6,%7}, {%8,%9}, {%0,%1,%2,%3};"
        : "+f"(d[0]), "+f"(d[1]), "+f"(d[2]), "+f"(d[3])
        : "r"(a[0]), "r"(a[1]), "r"(a[2]), "r"(a[3]), "r"(b[0]), "r"(b[1]));
}

__device__ __forceinline__ void wpair(__nv_bfloat16* dh, __nv_bfloat16* dl,
                                      size_t idx, float a0, float a1) {
    __nv_bfloat16 h0 = __float2bfloat16(a0), h1 = __float2bfloat16(a1);
    __nv_bfloat162 hv; hv.x = h0; hv.y = h1;
    __nv_bfloat162 lv;
    lv.x = __float2bfloat16(a0 - __bfloat162float(h0));
    lv.y = __float2bfloat16(a1 - __bfloat162float(h1));
    *(__nv_bfloat162*)(dh + idx) = hv;
    *(__nv_bfloat162*)(dl + idx) = lv;
}

// ---------------- weight transpose + split:  W[K,N] -> WT_hi/lo[N,K] -----
__global__ void wprep_kernel(const float* __restrict__ W,
                             __nv_bfloat16* __restrict__ Th,
                             __nv_bfloat16* __restrict__ Tl, int K, int N)
{
    int i = blockIdx.x * 256 + threadIdx.x;
    if (i >= K * N) return;
    int n = i / K, k = i - n * K;
    float v = W[(size_t)k * N + n];
    __nv_bfloat16 h = __float2bfloat16(v);
    Th[i] = h;
    Tl[i] = __float2bfloat16(v - __bfloat162float(h));
}

// ---------------- LayerNorm (+ roll + window gather), bf16 pair out ------
__global__ void ln_kernel(const float* __restrict__ src,
                          const float* __restrict__ gamma,
                          const float* __restrict__ beta,
                          __nv_bfloat16* __restrict__ dh,
                          __nv_bfloat16* __restrict__ dl, int gather)
{
    int gw = (blockIdx.x * blockDim.x + threadIdx.x) >> 5;
    if (gw >= TOK) return;
    int lane = threadIdx.x & 31;

    int srow;
    if (gather) {
        int w  = gw / SQ, s = gw - w * SQ;
        int bb = w >> 6, nw = w & 63;
        int wy = nw >> 3, wx = nw & 7;
        int iy = s / WSZ, ix = s - iy * WSZ;
        int row = wy * WSZ + iy + SHF; if (row >= HH)  row -= HH;
        int col = wx * WSZ + ix + SHF; if (col >= WWI) col -= WWI;
        srow = (bb * HH + row) * WWI + col;
    } else {
        srow = gw;
    }

    const float4* sp = (const float4*)(src + (size_t)srow * DIMC);
    float4 v[4];
    float sum = 0.f, sq = 0.f;
#pragma unroll
    for (int i = 0; i < 4; i++) {
        v[i] = sp[lane + i * 32];
        sum += v[i].x + v[i].y + v[i].z + v[i].w;
        sq  += v[i].x*v[i].x + v[i].y*v[i].y + v[i].z*v[i].z + v[i].w*v[i].w;
    }
#pragma unroll
    for (int o = 16; o > 0; o >>= 1) {
        sum += __shfl_xor_sync(0xffffffffu, sum, o);
        sq  += __shfl_xor_sync(0xffffffffu, sq,  o);
    }
    float mean = sum * (1.0f / DIMC);
    float var  = sq  * (1.0f / DIMC) - mean * mean;
    float inv  = rsqrtf(var + 1e-5f);

    const float4* gp = (const float4*)gamma;
    const float4* bp = (const float4*)beta;
    size_t rb = (size_t)gw * DIMC;
#pragma unroll
    for (int i = 0; i < 4; i++) {
        float4 g = gp[lane + i * 32];
        float4 b = bp[lane + i * 32];
        float o0 = (v[i].x - mean) * inv * g.x + b.x;
        float o1 = (v[i].y - mean) * inv * g.y + b.y;
        float o2 = (v[i].z - mean) * inv * g.z + b.z;
        float o3 = (v[i].w - mean) * inv * g.w + b.w;
        int e = (lane + i * 32) * 4;
        wpair(dh, dl, rb + e,     o0, o1);
        wpair(dh, dl, rb + e + 2, o2, o3);
    }
}

// ---------------- split-bf16 GEMM via mma.sync ---------------------------
// C[M,N] = A[M,K] * BT[N,K]^T, A/B bf16 (hi,lo) pairs, fp32 accumulate.
// EPI 0: +bias -> fp32 outF[row*N]
// EPI 1: +bias +add[map(row)] -> fp32 outF[map(row)]   (proj scatter, N=512)
// EPI 2: gelu(+bias) -> bf16 pair outH/outL
// EPI 3: +bias +add[row*N] -> fp32 outF[row*N]
#define GBM 128
#define GBN 128
#define GBK 32
#define STAGE  (32*1024)
#define OFF_AH 0
#define OFF_AL 8192
#define OFF_BH 16384
#define OFF_BL 24576
#define GEMM_SMEM (2*STAGE)

template<int EPI>
__device__ __forceinline__ void gemm_issue(
    uint32_t sb, char* smc_unused,
    const __nv_bfloat16* Ah, const __nv_bfloat16* Al,
    const __nv_bfloat16* Bh, const __nv_bfloat16* Bl,
    int bm0, int bn0, int K, int k0, int stage, int tid)
{
    uint32_t stb = sb + stage * STAGE;
#pragma unroll
    for (int i = 0; i < 2; i++) {
        int idx = i * 256 + tid;                    // 0..511
        int row = idx >> 2, cch = idx & 3;          // 128 rows x 4 chunks(16B)
        uint32_t soff = row * 64 + ((cch ^ ((row >> 1) & 3)) << 4);
        size_t ga = (size_t)(bm0 + row) * K + k0 + cch * 8;
        size_t gb = (size_t)(bn0 + row) * K + k0 + cch * 8;
        cpa16(stb + OFF_AH + soff, Ah + ga);
        cpa16(stb + OFF_AL + soff, Al + ga);
        cpa16(stb + OFF_BH + soff, Bh + gb);
        cpa16(stb + OFF_BL + soff, Bl + gb);
    }
    cp_commit();
}

template<int EPI>
__global__ void __launch_bounds__(256)
gemm_kernel(const __nv_bfloat16* __restrict__ Ah, const __nv_bfloat16* __restrict__ Al,
            const __nv_bfloat16* __restrict__ Bh, const __nv_bfloat16* __restrict__ Bl,
            const float* __restrict__ bias, const float* __restrict__ add,
            float* __restrict__ outF,
            __nv_bfloat16* __restrict__ outH, __nv_bfloat16* __restrict__ outL,
            int N, int K)
{
    extern __shared__ char smc[];
    uint32_t sb = smem_u32(smc);
    int tid  = threadIdx.x;
    int lane = tid & 31;
    int warp = tid >> 5;
    int wm = warp & 1, wn = warp >> 1;     // 2 x 4 warps, warp tile 64x32
    int bm0 = blockIdx.y * GBM;
    int bn0 = blockIdx.x * GBN;

    float acc[4][4][4];
#pragma unroll
    for (int a = 0; a < 4; a++)
#pragma unroll
        for (int b = 0; b < 4; b++)
#pragma unroll
            for (int c = 0; c < 4; c++) acc[a][b][c] = 0.f;

    int nch = K / GBK;
    gemm_issue<EPI>(sb, smc, Ah, Al, Bh, Bl, bm0, bn0, K, 0, 0, tid);

    for (int c = 0; c < nch; c++) {
        if (c + 1 < nch) {
            gemm_issue<EPI>(sb, smc, Ah, Al, Bh, Bl, bm0, bn0, K,
                            (c + 1) * GBK, (c + 1) & 1, tid);
            asm volatile("cp.async.wait_group 1;" ::: "memory");
        } else {
            asm volatile("cp.async.wait_group 0;" ::: "memory");
        }
        __syncthreads();

        uint32_t stb = sb + (c & 1) * STAGE;
#pragma unroll
        for (int ks = 0; ks < 2; ks++) {
            uint32_t ah[4][4], al[4][4], bh[4][2], bl[4][2];
#pragma unroll
            for (int mt = 0; mt < 4; mt++) {
                int row = wm * 64 + mt * 16 + (lane & 15);
                int kc  = ks * 2 + (lane >> 4);
                uint32_t ad = stb + OFF_AH + row * 64 + ((kc ^ ((row >> 1) & 3)) << 4);
                ldx4(ah[mt], ad);
                ldx4(al[mt], ad + (OFF_AL - OFF_AH));
            }
#pragma unroll
            for (int nt = 0; nt < 4; nt++) {
                int row = wn * 32 + nt * 8 + (lane & 7);
                int kc  = ks * 2 + ((lane >> 3) & 1);
                uint32_t bd = stb + OFF_BH + row * 64 + ((kc ^ ((row >> 1) & 3)) << 4);
                ldx2(bh[nt], bd);
                ldx2(bl[nt], bd + (OFF_BL - OFF_BH));
            }
#pragma unroll
            for (int mt = 0; mt < 4; mt++)
#pragma unroll
                for (int nt = 0; nt < 4; nt++) {
                    mma16816(acc[mt][nt], ah[mt], bh[nt]);
                    mma16816(acc[mt][nt], ah[mt], bl[nt]);
                    mma16816(acc[mt][nt], al[mt], bh[nt]);
                }
        }
        __syncthreads();
    }

    // -------- epilogue --------
#pragma unroll
    for (int mt = 0; mt < 4; mt++) {
        int r0 = bm0 + wm * 64 + mt * 16 + (lane >> 2);
#pragma unroll
        for (int half = 0; half < 2; half++) {
            int r = r0 + half * 8;
            size_t ob;
            if (EPI == 1) {
                int t = r, wi = t / SQ, s = t - wi * SQ;
                int bb2 = wi >> 6, nw = wi & 63;
                int wy = nw >> 3, wx = nw & 7;
                int iy = s / WSZ, ix = s - iy * WSZ;
                int rr = wy * WSZ + iy + SHF; if (rr >= HH)  rr -= HH;
                int cc2 = wx * WSZ + ix + SHF; if (cc2 >= WWI) cc2 -= WWI;
                ob = ((size_t)((bb2 * HH + rr) * WWI + cc2)) * DIMC;
            } else {
                ob = (size_t)r * N;
            }
#pragma unroll
            for (int nt = 0; nt < 4; nt++) {
                int cc = bn0 + wn * 32 + nt * 8 + (lane & 3) * 2;
                float v0 = acc[mt][nt][half * 2 + 0] + bias[cc];
                float v1 = acc[mt][nt][half * 2 + 1] + bias[cc + 1];
                if (EPI == 2) {
                    v0 = gelu_f(v0); v1 = gelu_f(v1);
                    wpair(outH, outL, (size_t)r * N + cc, v0, v1);
                } else {
                    if (EPI == 1 || EPI == 3) {
                        float2 a = *(const float2*)(add + ob + cc);
                        v0 += a.x; v1 += a.y;
                    }
                    float2 o; o.x = v0; o.y = v1;
                    *(float2*)(outF + ob + cc) = o;
                }
            }
        }
    }
}

// ---------------- attention: one block per (window, head), pair out ------
__global__ void __launch_bounds__(256)
attn_kernel(const float* __restrict__ qkv, const float* __restrict__ rel_bias,
            __nv_bfloat16* __restrict__ out_h, __nv_bfloat16* __restrict__ out_l)
{
    int w = blockIdx.x >> 4;
    int h = blockIdx.x & 15;

    __shared__ float sq[SQ][HDIM + 1];
    __shared__ float sk[SQ][HDIM + 1];
    __shared__ float sv[SQ][HDIM + 1];
    __shared__ float sp[8][64];
    __shared__ int   sm[SQ];

    const float scale = 0.17677669529663689f;
    int tid = threadIdx.x;

    for (int i = tid; i < SQ * HDIM; i += 256) {
        int s = i >> 5, d = i & 31;
        size_t base = ((size_t)(w * SQ + s)) * (3 * DIMC) + h * HDIM + d;
        sq[s][d] = qkv[base] * scale;
        sk[s][d] = qkv[base + DIMC];
        sv[s][d] = qkv[base + 2 * DIMC];
    }
    if (tid < SQ) {
        int nw = w & 63;
        int wy = nw >> 3, wx = nw & 7;
        int r = wy * WSZ + tid / WSZ;
        int c = wx * WSZ + tid % WSZ;
        int mr = (r < 49) ? 0 : ((r < 53) ? 1 : 2);
        int mc = (c < 49) ? 0 : ((c < 53) ? 1 : 2);
        sm[tid] = mr * 3 + mc;
    }
    __syncthreads();

    int wp = tid >> 5, lane = tid & 31;

    for (int i = wp; i < SQ; i += 8) {
        int yi = i / WSZ, xi = i - yi * WSZ;
        int mi = sm[i];

        float s1, s2 = -1e30f;
        {
            int j = lane;
            float acc = 0.f;
#pragma unroll
            for (int d = 0; d < HDIM; d++) acc += sq[i][d] * sk[j][d];
            int yj = j / WSZ, xj = j - yj * WSZ;
            int rpi = (yi - yj + 6) * 13 + (xi - xj + 6);
            acc += rel_bias[rpi * NHEAD + h];
            if (sm[j] != mi) acc -= 100.0f;
            s1 = acc;
        }
        int j2 = lane + 32;
        if (j2 < SQ) {
            float acc = 0.f;
#pragma unroll
            for (int d = 0; d < HDIM; d++) acc += sq[i][d] * sk[j2][d];
            int yj = j2 / WSZ, xj = j2 - yj * WSZ;
            int rpi = (yi - yj + 6) * 13 + (xi - xj + 6);
            acc += rel_bias[rpi * NHEAD + h];
            if (sm[j2] != mi) acc -= 100.0f;
            s2 = acc;
        }

        float m = fmaxf(s1, s2);
#pragma unroll
        for (int o = 16; o > 0; o >>= 1) m = fmaxf(m, __shfl_xor_sync(0xffffffffu, m, o));
        float e1 = expf(s1 - m);
        float e2 = (j2 < SQ) ? expf(s2 - m) : 0.f;
        float sum = e1 + e2;
#pragma unroll
        for (int o = 16; o > 0; o >>= 1) sum += __shfl_xor_sync(0xffffffffu, sum, o);
        float rinv = 1.0f / sum;

        sp[wp][lane] = e1 * rinv;
        if (j2 < 64) sp[wp][j2] = (j2 < SQ) ? e2 * rinv : 0.f;
        __syncwarp();

        float acc = 0.f;
#pragma unroll
        for (int j = 0; j < SQ; j++) acc += sp[wp][j] * sv[j][lane];
        size_t oi = ((size_t)(w * SQ + i)) * DIMC + h * HDIM + lane;
        __nv_bfloat16 hh = __float2bfloat16(acc);
        out_h[oi] = hh;
        out_l[oi] = __float2bfloat16(acc - __bfloat162float(hh));
        __syncwarp();
    }
}

// ---------------- launch --------------------------------------------------
extern "C" void kernel_launch(void* const* d_in, const int* in_sizes, int n_in,
                              void* d_out, int out_size)
{
    const float* x      = (const float*)d_in[0];
    const float* qkv_w  = (const float*)d_in[1];
    const float* qkv_b  = (const float*)d_in[2];
    const float* proj_w = (const float*)d_in[3];
    const float* proj_b = (const float*)d_in[4];
    const float* relb   = (const float*)d_in[5];
    const float* n1g    = (const float*)d_in[6];
    const float* n1b    = (const float*)d_in[7];
    const float* n2g    = (const float*)d_in[8];
    const float* n2b    = (const float*)d_in[9];
    const float* w1     = (const float*)d_in[10];
    const float* b1     = (const float*)d_in[11];
    const float* w2     = (const float*)d_in[12];
    const float* b2     = (const float*)d_in[13];
    float* out = (float*)d_out;

    __nv_bfloat16 *wth, *wtl, *winh, *winl, *atth, *attl, *ln2h, *ln2l, *m1h, *m1l;
    float *qkvs, *x1;
    cudaGetSymbolAddress((void**)&wth,  g_wt_h);
    cudaGetSymbolAddress((void**)&wtl,  g_wt_l);
    cudaGetSymbolAddress((void**)&winh, g_win_h);
    cudaGetSymbolAddress((void**)&winl, g_win_l);
    cudaGetSymbolAddress((void**)&qkvs, g_qkv);
    cudaGetSymbolAddress((void**)&atth, g_att_h);
    cudaGetSymbolAddress((void**)&attl, g_att_l);
    cudaGetSymbolAddress((void**)&x1,   g_x1);
    cudaGetSymbolAddress((void**)&ln2h, g_ln2_h);
    cudaGetSymbolAddress((void**)&ln2l, g_ln2_l);
    cudaGetSymbolAddress((void**)&m1h,  g_m1_h);
    cudaGetSymbolAddress((void**)&m1l,  g_m1_l);

    cudaFuncSetAttribute(gemm_kernel<0>, cudaFuncAttributeMaxDynamicSharedMemorySize, GEMM_SMEM);
    cudaFuncSetAttribute(gemm_kernel<1>, cudaFuncAttributeMaxDynamicSharedMemorySize, GEMM_SMEM);
    cudaFuncSetAttribute(gemm_kernel<2>, cudaFuncAttributeMaxDynamicSharedMemorySize, GEMM_SMEM);
    cudaFuncSetAttribute(gemm_kernel<3>, cudaFuncAttributeMaxDynamicSharedMemorySize, GEMM_SMEM);

    // weight transpose + bf16 split
    wprep_kernel<<<(512*1536 + 255)/256, 256>>>(qkv_w,  wth + OW_QKV,  wtl + OW_QKV,  512, 1536);
    wprep_kernel<<<(512*512  + 255)/256, 256>>>(proj_w, wth + OW_PROJ, wtl + OW_PROJ, 512, 512);
    wprep_kernel<<<(512*2048 + 255)/256, 256>>>(w1,     wth + OW_W1,   wtl + OW_W1,   512, 2048);
    wprep_kernel<<<(2048*512 + 255)/256, 256>>>(w2,     wth + OW_W2,   wtl + OW_W2,   2048, 512);

    const int lnBlocks = (TOK * 32) / 256;

    // 1. LN1 + roll + window partition -> bf16 pairs
    ln_kernel<<<lnBlocks, 256>>>(x, n1g, n1b, winh, winl, 1);

    // 2. QKV GEMM [TOK,512]x[512,1536] -> fp32
    gemm_kernel<0><<<dim3(1536/GBN, TOK/GBM), 256, GEMM_SMEM>>>(
        winh, winl, wth + OW_QKV, wtl + OW_QKV, qkv_b, nullptr,
        qkvs, nullptr, nullptr, 1536, 512);

    // 3. windowed attention -> bf16 pairs
    attn_kernel<<<WTOT * NHEAD, 256>>>(qkvs, relb, atth, attl);

    // 4. proj GEMM + fused window-reverse/unshift/skip/bias -> x1 (fp32)
    gemm_kernel<1><<<dim3(512/GBN, TOK/GBM), 256, GEMM_SMEM>>>(
        atth, attl, wth + OW_PROJ, wtl + OW_PROJ, proj_b, x,
        x1, nullptr, nullptr, 512, 512);

    // 5. LN2 -> bf16 pairs
    ln_kernel<<<lnBlocks, 256>>>(x1, n2g, n2b, ln2h, ln2l, 0);

    // 6. MLP1 GEMM + bias + exact GELU -> bf16 pairs
    gemm_kernel<2><<<dim3(MLPD/GBN, TOK/GBM), 256, GEMM_SMEM>>>(
        ln2h, ln2l, wth + OW_W1, wtl + OW_W1, b1, nullptr,
        nullptr, m1h, m1l, MLPD, 512);

    // 7. MLP2 GEMM + bias + residual -> out (fp32)
    gemm_kernel<3><<<dim3(512/GBN, TOK/GBM), 256, GEMM_SMEM>>>(
        m1h, m1l, wth + OW_W2, wtl + OW_W2, b2, x1,
        out, nullptr, nullptr, 512, 2048);
}

// round 4
// speedup vs baseline: 4.4379x; 2.1305x over previous
#include <cuda_runtime.h>
#include <cuda_fp16.h>
#include <cstdint>
#include <math.h>

// ---------------- problem constants ----------------
#define BB     32
#define HH     56
#define WWI    56
#define DIMC   512
#define WSZ    7
#define SHF    3
#define NHEAD  16
#define HDIM   32
#define MLPD   2048
#define SQ     49
#define TOK    (BB*HH*WWI)   // 100352
#define WTOT   (BB*64)       // 2048

// weight-transpose offsets (elements) in the packed wT array
#define OW_QKV  0
#define OW_PROJ (512*1536)
#define OW_W1   (OW_PROJ + 512*512)
#define OW_W2   (OW_W1 + 512*2048)
#define WT_TOT  (OW_W2 + 2048*512)

// ---------------- scratch ----------------
__device__ __half g_wt  [WT_TOT];
__device__ __half g_win [(size_t)TOK*DIMC];
__device__ float  g_qkv [(size_t)TOK*3*DIMC];
__device__ __half g_att [(size_t)TOK*DIMC];
__device__ float  g_x1  [(size_t)TOK*DIMC];
__device__ __half g_ln2 [(size_t)TOK*DIMC];
__device__ __half g_m1  [(size_t)TOK*MLPD];

__device__ __forceinline__ float gelu_f(float x) {
    return 0.5f * x * (1.0f + erff(x * 0.70710678118654752f));
}

// ---------------- PTX helpers (sm_80-era: valid on base sm_103) ----------
__device__ __forceinline__ uint32_t smem_u32(const void* p) {
    uint32_t a;
    asm("{ .reg .u64 t; cvta.to.shared.u64 t, %1; cvt.u32.u64 %0, t; }" : "=r"(a) : "l"(p));
    return a;
}
__device__ __forceinline__ void cpa16(uint32_t s, const void* g) {
    asm volatile("cp.async.cg.shared.global [%0], [%1], 16;" :: "r"(s), "l"(g));
}
__device__ __forceinline__ void cp_commit() {
    asm volatile("cp.async.commit_group;" ::: "memory");
}
__device__ __forceinline__ void ldx4(uint32_t* r, uint32_t a) {
    asm volatile("ldmatrix.sync.aligned.m8n8.x4.shared.b16 {%0,%1,%2,%3}, [%4];"
        : "=r"(r[0]), "=r"(r[1]), "=r"(r[2]), "=r"(r[3]) : "r"(a));
}
__device__ __forceinline__ void ldx2(uint32_t* r, uint32_t a) {
    asm volatile("ldmatrix.sync.aligned.m8n8.x2.shared.b16 {%0,%1}, [%2];"
        : "=r"(r[0]), "=r"(r[1]) : "r"(a));
}
__device__ __forceinline__ void mma16816(float* d, const uint32_t* a, const uint32_t* b) {
    asm volatile("mma.sync.aligned.m16n8k16.row.col.f32.f16.f16.f32 "
        "{%0,%1,%2,%3}, {%4,%5,%6,%7}, {%8,%9}, {%0,%1,%2,%3};"
        : "+f"(d[0]), "+f"(d[1]), "+f"(d[2]), "+f"(d[3])
        : "r"(a[0]), "r"(a[1]), "r"(a[2]), "r"(a[3]), "r"(b[0]), "r"(b[1]));
}

// ---------------- weight transpose:  W[K,N] -> WT[N,K] fp16 --------------
__global__ void wprep_kernel(const float* __restrict__ W,
                             __half* __restrict__ T, int K, int N)
{
    int i = blockIdx.x * 256 + threadIdx.x;
    if (i >= K * N) return;
    int n = i / K, k = i - n * K;
    T[i] = __float2half_rn(W[(size_t)k * N + n]);
}

// ---------------- LayerNorm (+ roll + window gather), fp16 out -----------
__global__ void ln_kernel(const float* __restrict__ src,
                          const float* __restrict__ gamma,
                          const float* __restrict__ beta,
                          __half* __restrict__ dst, int gather)
{
    int gw = (blockIdx.x * blockDim.x + threadIdx.x) >> 5;
    if (gw >= TOK) return;
    int lane = threadIdx.x & 31;

    int srow;
    if (gather) {
        int w  = gw / SQ, s = gw - w * SQ;
        int bb = w >> 6, nw = w & 63;
        int wy = nw >> 3, wx = nw & 7;
        int iy = s / WSZ, ix = s - iy * WSZ;
        int row = wy * WSZ + iy + SHF; if (row >= HH)  row -= HH;
        int col = wx * WSZ + ix + SHF; if (col >= WWI) col -= WWI;
        srow = (bb * HH + row) * WWI + col;
    } else {
        srow = gw;
    }

    const float4* sp = (const float4*)(src + (size_t)srow * DIMC);
    float4 v[4];
    float sum = 0.f, sq = 0.f;
#pragma unroll
    for (int i = 0; i < 4; i++) {
        v[i] = sp[lane + i * 32];
        sum += v[i].x + v[i].y + v[i].z + v[i].w;
        sq  += v[i].x*v[i].x + v[i].y*v[i].y + v[i].z*v[i].z + v[i].w*v[i].w;
    }
#pragma unroll
    for (int o = 16; o > 0; o >>= 1) {
        sum += __shfl_xor_sync(0xffffffffu, sum, o);
        sq  += __shfl_xor_sync(0xffffffffu, sq,  o);
    }
    float mean = sum * (1.0f / DIMC);
    float var  = sq  * (1.0f / DIMC) - mean * mean;
    float inv  = rsqrtf(var + 1e-5f);

    const float4* gp = (const float4*)gamma;
    const float4* bp = (const float4*)beta;
    size_t rb = (size_t)gw * DIMC;
#pragma unroll
    for (int i = 0; i < 4; i++) {
        float4 g = gp[lane + i * 32];
        float4 b = bp[lane + i * 32];
        __half2 h0, h1;
        h0.x = __float2half_rn((v[i].x - mean) * inv * g.x + b.x);
        h0.y = __float2half_rn((v[i].y - mean) * inv * g.y + b.y);
        h1.x = __float2half_rn((v[i].z - mean) * inv * g.z + b.z);
        h1.y = __float2half_rn((v[i].w - mean) * inv * g.w + b.w);
        int e = (lane + i * 32) * 4;
        *(__half2*)(dst + rb + e)     = h0;
        *(__half2*)(dst + rb + e + 2) = h1;
    }
}

// ---------------- fp16 GEMM via mma.sync ---------------------------------
// C[M,N] = A[M,K] * BT[N,K]^T, fp16 operands, fp32 accumulate.
// EPI 0: +bias -> fp32 outF[row*N]
// EPI 1: +bias +add[map(row)] -> fp32 outF[map(row)]   (proj scatter, N=512)
// EPI 2: gelu(+bias) -> fp16 outH
// EPI 3: +bias +add[row*N] -> fp32 outF[row*N]
#define GBM 128
#define GBN 128
#define GBK 64
#define STAGE  (32*1024)
#define OFF_A  0
#define OFF_B  16384
#define GEMM_SMEM (2*STAGE)

__device__ __forceinline__ void gemm_issue(
    uint32_t sb, const __half* A, const __half* B,
    int bm0, int bn0, int K, int k0, int stage, int tid)
{
    uint32_t stb = sb + stage * STAGE;
#pragma unroll
    for (int i = 0; i < 4; i++) {
        int idx = i * 256 + tid;                    // 0..1023
        int row = idx >> 3, cch = idx & 7;          // 128 rows x 8 chunks(16B)
        uint32_t soff = row * 128 + ((cch ^ (row & 7)) << 4);
        cpa16(stb + OFF_A + soff, A + (size_t)(bm0 + row) * K + k0 + cch * 8);
        cpa16(stb + OFF_B + soff, B + (size_t)(bn0 + row) * K + k0 + cch * 8);
    }
    cp_commit();
}

template<int EPI>
__global__ void __launch_bounds__(256, 2)
gemm_kernel(const __half* __restrict__ A, const __half* __restrict__ B,
            const float* __restrict__ bias, const float* __restrict__ add,
            float* __restrict__ outF, __half* __restrict__ outH,
            int N, int K)
{
    extern __shared__ char smc[];
    uint32_t sb = smem_u32(smc);
    int tid  = threadIdx.x;
    int lane = tid & 31;
    int warp = tid >> 5;
    int wm = warp & 1, wn = warp >> 1;     // 2 x 4 warps, warp tile 64x32
    int bm0 = blockIdx.y * GBM;
    int bn0 = blockIdx.x * GBN;

    float acc[4][4][4];
#pragma unroll
    for (int a = 0; a < 4; a++)
#pragma unroll
        for (int b = 0; b < 4; b++)
#pragma unroll
            for (int c = 0; c < 4; c++) acc[a][b][c] = 0.f;

    int nch = K / GBK;
    gemm_issue(sb, A, B, bm0, bn0, K, 0, 0, tid);

    for (int c = 0; c < nch; c++) {
        if (c + 1 < nch) {
            gemm_issue(sb, A, B, bm0, bn0, K, (c + 1) * GBK, (c + 1) & 1, tid);
            asm volatile("cp.async.wait_group 1;" ::: "memory");
        } else {
            asm volatile("cp.async.wait_group 0;" ::: "memory");
        }
        __syncthreads();

        uint32_t stb = sb + (c & 1) * STAGE;
#pragma unroll
        for (int ks = 0; ks < 4; ks++) {
            uint32_t ah[4][4], bh[4][2];
#pragma unroll
            for (int mt = 0; mt < 4; mt++) {
                int row = wm * 64 + mt * 16 + (lane & 15);
                int kc  = ks * 2 + (lane >> 4);
                ldx4(ah[mt], stb + OFF_A + row * 128 + ((kc ^ (row & 7)) << 4));
            }
#pragma unroll
            for (int nt = 0; nt < 4; nt++) {
                int row = wn * 32 + nt * 8 + (lane & 7);
                int kc  = ks * 2 + ((lane >> 3) & 1);
                ldx2(bh[nt], stb + OFF_B + row * 128 + ((kc ^ (row & 7)) << 4));
            }
#pragma unroll
            for (int mt = 0; mt < 4; mt++)
#pragma unroll
                for (int nt = 0; nt < 4; nt++)
                    mma16816(acc[mt][nt], ah[mt], bh[nt]);
        }
        __syncthreads();
    }

    // -------- epilogue --------
#pragma unroll
    for (int mt = 0; mt < 4; mt++) {
        int r0 = bm0 + wm * 64 + mt * 16 + (lane >> 2);
#pragma unroll
        for (int half_ = 0; half_ < 2; half_++) {
            int r = r0 + half_ * 8;
            size_t ob;
            if (EPI == 1) {
                int t = r, wi = t / SQ, s = t - wi * SQ;
                int bb2 = wi >> 6, nw = wi & 63;
                int wy = nw >> 3, wx = nw & 7;
                int iy = s / WSZ, ix = s - iy * WSZ;
                int rr = wy * WSZ + iy + SHF; if (rr >= HH)  rr -= HH;
                int cc2 = wx * WSZ + ix + SHF; if (cc2 >= WWI) cc2 -= WWI;
                ob = ((size_t)((bb2 * HH + rr) * WWI + cc2)) * DIMC;
            } else {
                ob = (size_t)r * N;
            }
#pragma unroll
            for (int nt = 0; nt < 4; nt++) {
                int cc = bn0 + wn * 32 + nt * 8 + (lane & 3) * 2;
                float v0 = acc[mt][nt][half_ * 2 + 0] + bias[cc];
                float v1 = acc[mt][nt][half_ * 2 + 1] + bias[cc + 1];
                if (EPI == 2) {
                    __half2 hv;
                    hv.x = __float2half_rn(gelu_f(v0));
                    hv.y = __float2half_rn(gelu_f(v1));
                    *(__half2*)(outH + (size_t)r * N + cc) = hv;
                } else {
                    if (EPI == 1 || EPI == 3) {
                        float2 a = *(const float2*)(add + ob + cc);
                        v0 += a.x; v1 += a.y;
                    }
                    float2 o; o.x = v0; o.y = v1;
                    *(float2*)(outF + ob + cc) = o;
                }
            }
        }
    }
}

// ---------------- attention: one block per (window, head), fp16 out ------
__global__ void __launch_bounds__(256)
attn_kernel(const float* __restrict__ qkv, const float* __restrict__ rel_bias,
            __half* __restrict__ out_h)
{
    int w = blockIdx.x >> 4;
    int h = blockIdx.x & 15;

    __shared__ float sq[SQ][HDIM + 1];
    __shared__ float sk[SQ][HDIM + 1];
    __shared__ float sv[SQ][HDIM + 1];
    __shared__ float sp[8][64];
    __shared__ int   sm[SQ];

    const float scale = 0.17677669529663689f;
    int tid = threadIdx.x;

    for (int i = tid; i < SQ * HDIM; i += 256) {
        int s = i >> 5, d = i & 31;
        size_t base = ((size_t)(w * SQ + s)) * (3 * DIMC) + h * HDIM + d;
        sq[s][d] = qkv[base] * scale;
        sk[s][d] = qkv[base + DIMC];
        sv[s][d] = qkv[base + 2 * DIMC];
    }
    if (tid < SQ) {
        int nw = w & 63;
        int wy = nw >> 3, wx = nw & 7;
        int r = wy * WSZ + tid / WSZ;
        int c = wx * WSZ + tid % WSZ;
        int mr = (r < 49) ? 0 : ((r < 53) ? 1 : 2);
        int mc = (c < 49) ? 0 : ((c < 53) ? 1 : 2);
        sm[tid] = mr * 3 + mc;
    }
    __syncthreads();

    int wp = tid >> 5, lane = tid & 31;

    for (int i = wp; i < SQ; i += 8) {
        int yi = i / WSZ, xi = i - yi * WSZ;
        int mi = sm[i];

        float s1, s2 = -1e30f;
        {
            int j = lane;
            float acc = 0.f;
#pragma unroll
            for (int d = 0; d < HDIM; d++) acc += sq[i][d] * sk[j][d];
            int yj = j / WSZ, xj = j - yj * WSZ;
            int rpi = (yi - yj + 6) * 13 + (xi - xj + 6);
            acc += rel_bias[rpi * NHEAD + h];
            if (sm[j] != mi) acc -= 100.0f;
            s1 = acc;
        }
        int j2 = lane + 32;
        if (j2 < SQ) {
            float acc = 0.f;
#pragma unroll
            for (int d = 0; d < HDIM; d++) acc += sq[i][d] * sk[j2][d];
            int yj = j2 / WSZ, xj = j2 - yj * WSZ;
            int rpi = (yi - yj + 6) * 13 + (xi - xj + 6);
            acc += rel_bias[rpi * NHEAD + h];
            if (sm[j2] != mi) acc -= 100.0f;
            s2 = acc;
        }

        float m = fmaxf(s1, s2);
#pragma unroll
        for (int o = 16; o > 0; o >>= 1) m = fmaxf(m, __shfl_xor_sync(0xffffffffu, m, o));
        float e1 = expf(s1 - m);
        float e2 = (j2 < SQ) ? expf(s2 - m) : 0.f;
        float sum = e1 + e2;
#pragma unroll
        for (int o = 16; o > 0; o >>= 1) sum += __shfl_xor_sync(0xffffffffu, sum, o);
        float rinv = 1.0f / sum;

        sp[wp][lane] = e1 * rinv;
        if (j2 < 64) sp[wp][j2] = (j2 < SQ) ? e2 * rinv : 0.f;
        __syncwarp();

        float acc = 0.f;
#pragma unroll
        for (int j = 0; j < SQ; j++) acc += sp[wp][j] * sv[j][lane];
        out_h[((size_t)(w * SQ + i)) * DIMC + h * HDIM + lane] = __float2half_rn(acc);
        __syncwarp();
    }
}

// ---------------- launch --------------------------------------------------
extern "C" void kernel_launch(void* const* d_in, const int* in_sizes, int n_in,
                              void* d_out, int out_size)
{
    const float* x      = (const float*)d_in[0];
    const float* qkv_w  = (const float*)d_in[1];
    const float* qkv_b  = (const float*)d_in[2];
    const float* proj_w = (const float*)d_in[3];
    const float* proj_b = (const float*)d_in[4];
    const float* relb   = (const float*)d_in[5];
    const float* n1g    = (const float*)d_in[6];
    const float* n1b    = (const float*)d_in[7];
    const float* n2g    = (const float*)d_in[8];
    const float* n2b    = (const float*)d_in[9];
    const float* w1     = (const float*)d_in[10];
    const float* b1     = (const float*)d_in[11];
    const float* w2     = (const float*)d_in[12];
    const float* b2     = (const float*)d_in[13];
    float* out = (float*)d_out;

    __half *wt, *win, *att, *ln2s, *m1;
    float *qkvs, *x1;
    cudaGetSymbolAddress((void**)&wt,   g_wt);
    cudaGetSymbolAddress((void**)&win,  g_win);
    cudaGetSymbolAddress((void**)&qkvs, g_qkv);
    cudaGetSymbolAddress((void**)&att,  g_att);
    cudaGetSymbolAddress((void**)&x1,   g_x1);
    cudaGetSymbolAddress((void**)&ln2s, g_ln2);
    cudaGetSymbolAddress((void**)&m1,   g_m1);

    cudaFuncSetAttribute(gemm_kernel<0>, cudaFuncAttributeMaxDynamicSharedMemorySize, GEMM_SMEM);
    cudaFuncSetAttribute(gemm_kernel<1>, cudaFuncAttributeMaxDynamicSharedMemorySize, GEMM_SMEM);
    cudaFuncSetAttribute(gemm_kernel<2>, cudaFuncAttributeMaxDynamicSharedMemorySize, GEMM_SMEM);
    cudaFuncSetAttribute(gemm_kernel<3>, cudaFuncAttributeMaxDynamicSharedMemorySize, GEMM_SMEM);

    // weight transpose -> fp16
    wprep_kernel<<<(512*1536 + 255)/256, 256>>>(qkv_w,  wt + OW_QKV,  512, 1536);
    wprep_kernel<<<(512*512  + 255)/256, 256>>>(proj_w, wt + OW_PROJ, 512, 512);
    wprep_kernel<<<(512*2048 + 255)/256, 256>>>(w1,     wt + OW_W1,   512, 2048);
    wprep_kernel<<<(2048*512 + 255)/256, 256>>>(w2,     wt + OW_W2,   2048, 512);

    const int lnBlocks = (TOK * 32) / 256;

    // 1. LN1 + roll + window partition -> fp16
    ln_kernel<<<lnBlocks, 256>>>(x, n1g, n1b, win, 1);

    // 2. QKV GEMM [TOK,512]x[512,1536] -> fp32
    gemm_kernel<0><<<dim3(1536/GBN, TOK/GBM), 256, GEMM_SMEM>>>(
        win, wt + OW_QKV, qkv_b, nullptr, qkvs, nullptr, 1536, 512);

    // 3. windowed attention -> fp16
    attn_kernel<<<WTOT * NHEAD, 256>>>(qkvs, relb, att);

    // 4. proj GEMM + fused window-reverse/unshift/skip/bias -> x1 (fp32)
    gemm_kernel<1><<<dim3(512/GBN, TOK/GBM), 256, GEMM_SMEM>>>(
        att, wt + OW_PROJ, proj_b, x, x1, nullptr, 512, 512);

    // 5. LN2 -> fp16
    ln_kernel<<<lnBlocks, 256>>>(x1, n2g, n2b, ln2s, 0);

    // 6. MLP1 GEMM + bias + exact GELU -> fp16
    gemm_kernel<2><<<dim3(MLPD/GBN, TOK/GBM), 256, GEMM_SMEM>>>(
        ln2s, wt + OW_W1, b1, nullptr, nullptr, m1, MLPD, 512);

    // 7. MLP2 GEMM + bias + residual -> out (fp32)
    gemm_kernel<3><<<dim3(512/GBN, TOK/GBM), 256, GEMM_SMEM>>>(
        m1, wt + OW_W2, b2, x1, out, nullptr, 512, 2048);
}